// round 9
// baseline (speedup 1.0000x reference)
#include <cuda_runtime.h>
#include <math.h>

#define WW 512
#define HH 512
#define NIMG 8
#define HWSZ (HH * WW)
#define NPLANES 16            // 2 streams (p, target) x 8 samples
#define TOTALSZ (NPLANES * HWSZ)
#define NITER 50

#define STRIPS 5              // 5 strips x 120 output cols (lanes 1..30 of 32x float4)
#define CHUNK_ROWS 16
#define CHUNKS 32             // 512 / 16

// open-init sweep config (one plane per warp)
#define WARPS_TOTAL (STRIPS * CHUNKS * NPLANES)   // 2560
#define SWEEP_BLOCK 256
#define SWEEP_GRID (WARPS_TOTAL / (SWEEP_BLOCK / 32))  // 320

// fused-2 iteration config: TWO planes per warp (z and z+8)
#define WARPS_IT2 (STRIPS * CHUNKS * NIMG)        // 1280
#define IT2_BLOCK 128
#define IT2_GRID (WARPS_IT2 / (IT2_BLOCK / 32))   // 320

// Static scratch (no allocations allowed in kernel_launch)
__device__ float g_p[NIMG * HWSZ];     // sigmoid(output), kept for final reduction
__device__ float g_imgA[TOTALSZ];      // ping
__device__ float g_imgB[TOTALSZ];      // pong
__device__ float g_skel[TOTALSZ];      // skeleton accumulators (both streams)
__device__ double g_sums[NIMG][7];     // per-sample reduction accumulators

// ---------------------------------------------------------------------------
// float4 helpers
// ---------------------------------------------------------------------------
__device__ __forceinline__ float4 f44(float v) { return make_float4(v, v, v, v); }
__device__ __forceinline__ float4 min4(float4 a, float4 b) {
    return make_float4(fminf(a.x, b.x), fminf(a.y, b.y), fminf(a.z, b.z), fminf(a.w, b.w));
}
__device__ __forceinline__ float4 max4(float4 a, float4 b) {
    return make_float4(fmaxf(a.x, b.x), fmaxf(a.y, b.y), fmaxf(a.z, b.z), fmaxf(a.w, b.w));
}
__device__ __forceinline__ float4 vmin3(float4 a, float4 b, float4 c) { return min4(min4(a, b), c); }
__device__ __forceinline__ float4 vmax3(float4 a, float4 b, float4 c) { return max4(max4(a, b), c); }
__device__ __forceinline__ float4 hmin3(float4 v, int lane) {
    float L = __shfl_up_sync(0xffffffffu, v.w, 1);
    float R = __shfl_down_sync(0xffffffffu, v.x, 1);
    if (lane == 0)  L = INFINITY;
    if (lane == 31) R = INFINITY;
    float m01 = fminf(v.x, v.y), m23 = fminf(v.z, v.w);
    return make_float4(fminf(L, m01), fminf(m01, v.z), fminf(v.y, m23), fminf(m23, R));
}
__device__ __forceinline__ float4 hmax3(float4 v, int lane) {
    float L = __shfl_up_sync(0xffffffffu, v.w, 1);
    float R = __shfl_down_sync(0xffffffffu, v.x, 1);
    if (lane == 0)  L = -INFINITY;
    if (lane == 31) R = -INFINITY;
    float m01 = fmaxf(v.x, v.y), m23 = fmaxf(v.z, v.w);
    return make_float4(fmaxf(L, m01), fmaxf(m01, v.z), fmaxf(v.y, m23), fmaxf(m23, R));
}
__device__ __forceinline__ float4 relu_sub(float4 a, float4 b) {
    return make_float4(fmaxf(0.0f, a.x - b.x), fmaxf(0.0f, a.y - b.y),
                       fmaxf(0.0f, a.z - b.z), fmaxf(0.0f, a.w - b.w));
}
__device__ __forceinline__ float4 maskneg(float4 v, bool ok) {
    return ok ? v : f44(-INFINITY);
}
__device__ __forceinline__ void skel_upd(float4& s, float4 d) {
    s.x += fmaxf(0.0f, fmaf(-s.x, d.x, d.x));
    s.y += fmaxf(0.0f, fmaf(-s.y, d.y, d.y));
    s.z += fmaxf(0.0f, fmaf(-s.z, d.z, d.z));
    s.w += fmaxf(0.0f, fmaf(-s.w, d.w, d.w));
}

// ---------------------------------------------------------------------------
// Init: p = sigmoid(output); imgA[stream0] = p, imgA[stream1] = target
// ---------------------------------------------------------------------------
__global__ void k_init(const float4* __restrict__ out, const float4* __restrict__ tgt) {
    int i = blockIdx.x * blockDim.x + threadIdx.x;
    int stride = gridDim.x * blockDim.x;
    float4* gp = (float4*)g_p;
    float4* ga = (float4*)g_imgA;
    float4* gb = (float4*)(g_imgA + NIMG * HWSZ);
    const int n4 = NIMG * HWSZ / 4;
    for (; i < n4; i += stride) {
        float4 o = out[i];
        float4 v;
        v.x = 1.0f / (1.0f + expf(-o.x));
        v.y = 1.0f / (1.0f + expf(-o.y));
        v.z = 1.0f / (1.0f + expf(-o.z));
        v.w = 1.0f / (1.0f + expf(-o.w));
        gp[i] = v;
        ga[i] = v;
        gb[i] = tgt[i];
    }
}

// ---------------------------------------------------------------------------
// Warp-sweep open-init:  skel = relu(img - dilate(erode(img)))
// ---------------------------------------------------------------------------
__global__ void __launch_bounds__(SWEEP_BLOCK, 3) k_open_init() {
    const int lane = threadIdx.x & 31;
    const int gw = (blockIdx.x * SWEEP_BLOCK + threadIdx.x) >> 5;
    const int strip = gw % STRIPS;
    const int t = gw / STRIPS;
    const int chunk = t & (CHUNKS - 1);
    const int z = t >> 5;

    const float* __restrict__ src = g_imgA + z * HWSZ;
    float* __restrict__ skel = g_skel + z * HWSZ;

    const int c0 = strip * 120 - 4 + 4 * lane;
    const bool colok = (c0 >= 0) && (c0 < WW);
    const bool stok = (lane >= 1) && (lane <= 30) && (c0 < WW);
    const int r0 = chunk * CHUNK_ROWS;
    const int ylim = r0 + 2;

    int y = r0 - 2;
    const float* srcp = src + y * WW + c0;
    float* const skb = skel + c0;

    float4 ia = f44(INFINITY), ib = f44(INFINITY), ic;
    float4 ha = f44(-INFINITY), hb = f44(-INFINITY), hc;

#define OPEN_STEP(IA, IB, IC, HA, HB, HC)                                      \
    {                                                                          \
        bool ldok = colok && ((unsigned)y < (unsigned)HH);                     \
        IC = ldok ? *(const float4*)srcp : f44(INFINITY);                      \
        float4 e1_ = min4(vmin3(IA, IB, IC), hmin3(IB, lane));                 \
        if (!colok || (unsigned)(y - 1) >= (unsigned)HH) e1_ = f44(-INFINITY); \
        HC = hmax3(e1_, lane);                                                 \
        if (y >= ylim) {                                                       \
            float4 d_ = vmax3(HA, HB, HC);                                     \
            if (stok) {                                                        \
                float4 o_ = relu_sub(IA, d_);                                  \
                *(float4*)(skb + (y - 2) * WW) = o_;                           \
            }                                                                  \
        }                                                                      \
        ++y;                                                                   \
        srcp += WW;                                                            \
    }

#pragma unroll 1
    for (int k = 0; k < 6; ++k) {
        OPEN_STEP(ia, ib, ic, ha, hb, hc);
        OPEN_STEP(ib, ic, ia, hb, hc, ha);
        OPEN_STEP(ic, ia, ib, hc, ha, hb);
    }
    OPEN_STEP(ia, ib, ic, ha, hb, hc);
    OPEN_STEP(ib, ic, ia, hb, hc, ha);
#undef OPEN_STEP
}

// ---------------------------------------------------------------------------
// One pipeline step of the fused-2 iteration for ONE plane (float4 lanes).
// Called twice per y (two independent planes) to double per-warp ILP.
// ---------------------------------------------------------------------------
__device__ __forceinline__ void step_f4(
    float4& IA, float4& IB, float4& IC,
    float4& EA, float4& EB, float4& EC,
    float4& FA, float4& FB, float4& FC,
    float4& HA, float4& HB, float4& HC,
    float4& BA, float4& BB, float4& BC,
    float4& pf, float4& dprev, float4& spf,
    const float*& srcp, float* skb, float* dsb,
    int y, int lane, bool colok, bool stok, int yD1, int yOUT)
{
    float4 icur = pf;
    {
        bool ldok = colok && ((unsigned)(y + 1) < (unsigned)HH);
        pf = ldok ? *(const float4*)srcp : f44(INFINITY);
        srcp += WW;
    }
    IC = icur;
    EC = min4(vmin3(IA, IB, IC), hmin3(IB, lane));          /* E1[y-1] */
    FC = min4(vmin3(EA, EB, EC), hmin3(EB, lane));          /* E2[y-2] */
    HC = hmax3(maskneg(FC, colok && (unsigned)(y - 2) < (unsigned)HH), lane);
    float4 e3_ = min4(vmin3(FA, FB, FC), hmin3(FB, lane));  /* E3[y-3] */
    BC = hmax3(maskneg(e3_, colok && (unsigned)(y - 3) < (unsigned)HH), lane);
    if (y >= yOUT) {                                        /* row y-4 */
        float4 D2 = vmax3(BA, BB, BC);
        if (stok) {
            float4 d2 = relu_sub(FA, D2);                   /* E2[y-4] */
            float4 s = spf;
            skel_upd(s, dprev);
            skel_upd(s, d2);
            *(float4*)(skb + (y - 4) * WW) = s;
            *(float4*)(dsb + (y - 4) * WW) = FA;
        }
    }
    if (y >= yD1) {                                         /* delta1 y-3 */
        float4 D1 = vmax3(HA, HB, HC);
        dprev = relu_sub(EA, D1);                           /* E1[y-3] */
        if (stok && (unsigned)(y - 3) < (unsigned)HH)
            spf = *(const float4*)(skb + (y - 3) * WW);
    }
}

// ---------------------------------------------------------------------------
// Fused TWO skeleton iterations; each warp sweeps the SAME strip/chunk of TWO
// independent planes (z and z+8) to provide two independent dependency chains.
// ---------------------------------------------------------------------------
__global__ void __launch_bounds__(IT2_BLOCK, 3) k_iter2(int flip) {
    const int lane = threadIdx.x & 31;
    const int gw = (blockIdx.x * IT2_BLOCK + threadIdx.x) >> 5;
    const int strip = gw % STRIPS;
    const int t = gw / STRIPS;
    const int chunk = t & (CHUNKS - 1);
    const int zz = t >> 5;                     // 0..7

    const float* baseS = flip ? g_imgB : g_imgA;
    float* baseD = flip ? g_imgA : g_imgB;

    const int c0 = strip * 120 - 4 + 4 * lane;
    const bool colok = (c0 >= 0) && (c0 < WW);
    const bool stok = (lane >= 1) && (lane <= 30) && (c0 < WW);
    const int r0 = chunk * CHUNK_ROWS;
    const int yD1 = r0 + 3;
    const int yOUT = r0 + 4;

    const int offA = zz * HWSZ;
    const int offB = (zz + NIMG) * HWSZ;

    int y = r0 - 4;
    // plane A state
    const float* srcpA = baseS + offA + y * WW + c0;
    float* const skbA = g_skel + offA + c0;
    float* const dsbA = baseD + offA + c0;
    // plane B state
    const float* srcpB = baseS + offB + y * WW + c0;
    float* const skbB = g_skel + offB + c0;
    float* const dsbB = baseD + offB + c0;

    float4 pfA, pfB;
    {
        bool ldok = colok && ((unsigned)y < (unsigned)HH);
        pfA = ldok ? *(const float4*)srcpA : f44(INFINITY);
        pfB = ldok ? *(const float4*)srcpB : f44(INFINITY);
    }
    srcpA += WW;
    srcpB += WW;

    float4 ia = f44(INFINITY), ib = f44(INFINITY), ic;
    float4 ea = f44(INFINITY), eb = f44(INFINITY), ec;
    float4 fa = f44(INFINITY), fb = f44(INFINITY), fc;
    float4 ha = f44(-INFINITY), hb = f44(-INFINITY), hc;
    float4 ba = f44(-INFINITY), bb = f44(-INFINITY), bc;
    float4 dpA = f44(0.0f), spA = f44(0.0f);

    float4 ja = f44(INFINITY), jb = f44(INFINITY), jc;
    float4 ka = f44(INFINITY), kb = f44(INFINITY), kc;
    float4 la = f44(INFINITY), lb = f44(INFINITY), lc;
    float4 ma = f44(-INFINITY), mb = f44(-INFINITY), mc;
    float4 na = f44(-INFINITY), nb = f44(-INFINITY), nc;
    float4 dpB = f44(0.0f), spB = f44(0.0f);

#define DSTEP(A0,A1,A2, B0,B1,B2, C0,C1,C2, D0,D1,D2, E0,E1,E2,                \
              P0,P1,P2, Q0,Q1,Q2, R0,R1,R2, S0,S1,S2, T0,T1,T2)                \
    {                                                                          \
        step_f4(A0,A1,A2, B0,B1,B2, C0,C1,C2, D0,D1,D2, E0,E1,E2,              \
                pfA, dpA, spA, srcpA, skbA, dsbA,                              \
                y, lane, colok, stok, yD1, yOUT);                              \
        step_f4(P0,P1,P2, Q0,Q1,Q2, R0,R1,R2, S0,S1,S2, T0,T1,T2,              \
                pfB, dpB, spB, srcpB, skbB, dsbB,                              \
                y, lane, colok, stok, yD1, yOUT);                              \
        ++y;                                                                   \
    }

#pragma unroll 1
    for (int k = 0; k < 8; ++k) {
        DSTEP(ia,ib,ic, ea,eb,ec, fa,fb,fc, ha,hb,hc, ba,bb,bc,
              ja,jb,jc, ka,kb,kc, la,lb,lc, ma,mb,mc, na,nb,nc);
        DSTEP(ib,ic,ia, eb,ec,ea, fb,fc,fa, hb,hc,ha, bb,bc,ba,
              jb,jc,ja, kb,kc,ka, lb,lc,la, mb,mc,ma, nb,nc,na);
        DSTEP(ic,ia,ib, ec,ea,eb, fc,fa,fb, hc,ha,hb, bc,ba,bb,
              jc,ja,jb, kc,ka,kb, lc,la,lb, mc,ma,mb, nc,na,nb);
    }
#undef DSTEP
}

// ---------------------------------------------------------------------------
// Reductions
// ---------------------------------------------------------------------------
__global__ void k_zero() {
    int t = threadIdx.x;
    if (t < NIMG * 7) ((double*)g_sums)[t] = 0.0;
}

__global__ void k_reduce(const float* __restrict__ tgt) {
    const int n = blockIdx.y;
    const float4* __restrict__ sp = (const float4*)(g_skel + n * HWSZ);
    const float4* __restrict__ sl = (const float4*)(g_skel + (NIMG + n) * HWSZ);
    const float4* __restrict__ pp = (const float4*)(g_p + n * HWSZ);
    const float4* __restrict__ tt = (const float4*)(tgt + n * HWSZ);
    const int n4 = HWSZ / 4;

    double a0 = 0, a1 = 0, a2 = 0, a3 = 0, a4 = 0, a5 = 0, a6 = 0;
    for (int i = blockIdx.x * blockDim.x + threadIdx.x; i < n4;
         i += gridDim.x * blockDim.x) {
        float4 s1 = sp[i], s2 = sl[i], pv = pp[i], tv = tt[i];
        a0 += (double)(s1.x * tv.x + s1.y * tv.y + s1.z * tv.z + s1.w * tv.w);
        a1 += (double)(s1.x + s1.y + s1.z + s1.w);
        a2 += (double)(s2.x * pv.x + s2.y * pv.y + s2.z * pv.z + s2.w * pv.w);
        a3 += (double)(s2.x + s2.y + s2.z + s2.w);
        a4 += (double)(pv.x * tv.x + pv.y * tv.y + pv.z * tv.z + pv.w * tv.w);
        a5 += (double)(pv.x + pv.y + pv.z + pv.w);
        a6 += (double)(tv.x + tv.y + tv.z + tv.w);
    }
#pragma unroll
    for (int o = 16; o > 0; o >>= 1) {
        a0 += __shfl_down_sync(0xffffffffu, a0, o);
        a1 += __shfl_down_sync(0xffffffffu, a1, o);
        a2 += __shfl_down_sync(0xffffffffu, a2, o);
        a3 += __shfl_down_sync(0xffffffffu, a3, o);
        a4 += __shfl_down_sync(0xffffffffu, a4, o);
        a5 += __shfl_down_sync(0xffffffffu, a5, o);
        a6 += __shfl_down_sync(0xffffffffu, a6, o);
    }
    if ((threadIdx.x & 31) == 0) {
        atomicAdd(&g_sums[n][0], a0);
        atomicAdd(&g_sums[n][1], a1);
        atomicAdd(&g_sums[n][2], a2);
        atomicAdd(&g_sums[n][3], a3);
        atomicAdd(&g_sums[n][4], a4);
        atomicAdd(&g_sums[n][5], a5);
        atomicAdd(&g_sums[n][6], a6);
    }
}

__global__ void k_final(float* __restrict__ out, int out_size) {
    if (threadIdx.x == 0 && blockIdx.x == 0) {
        const double smooth = 1.0;
        double cl = 0.0, dice = 0.0;
        for (int n = 0; n < NIMG; n++) {
            double A = g_sums[n][0], B = g_sums[n][1], C = g_sums[n][2],
                   D = g_sums[n][3], E = g_sums[n][4], F = g_sums[n][5],
                   G = g_sums[n][6];
            double tprec = (A + smooth) / (B + smooth);
            double tsens = (C + smooth) / (D + smooth);
            cl += 1.0 - 2.0 * tprec * tsens / (tprec + tsens);
            dice += 1.0 - 2.0 * (E + smooth) / (F + G + smooth);
        }
        cl /= NIMG;
        dice /= NIMG;
        float loss = (float)(0.7 * dice + 0.3 * cl);
        for (int i = 0; i < out_size; i++) out[i] = loss;
    }
}

// ---------------------------------------------------------------------------
extern "C" void kernel_launch(void* const* d_in, const int* in_sizes, int n_in,
                              void* d_out, int out_size) {
    const float* output = (const float*)d_in[0];
    const float* target = (const float*)d_in[1];
    float* out = (float*)d_out;

    k_init<<<1024, 256>>>((const float4*)output, (const float4*)target);

    k_open_init<<<SWEEP_GRID, SWEEP_BLOCK>>>();

    // 50 iterations = 25 fused-2 launches
    for (int j = 0; j < NITER / 2; ++j) {
        k_iter2<<<IT2_GRID, IT2_BLOCK>>>(j & 1);
    }

    k_zero<<<1, 64>>>();
    k_reduce<<<dim3(32, NIMG), 256>>>(target);
    k_final<<<1, 32>>>(out, out_size);
}

// round 10
// speedup vs baseline: 1.0870x; 1.0870x over previous
#include <cuda_runtime.h>
#include <math.h>

#define WW 512
#define HH 512
#define NIMG 8
#define HWSZ (HH * WW)
#define NPLANES 16            // 2 streams (p, target) x 8 samples
#define TOTALSZ (NPLANES * HWSZ)
#define NITER 50

#define STRIPS 5              // 5 strips x 120 output cols (lanes 1..30 of 32x float4)
#define CHUNK_ROWS 16
#define CHUNKS 32             // 512 / 16
#define WARPS_TOTAL (STRIPS * CHUNKS * NPLANES)   // 2560

// open-init sweep config
#define SWEEP_BLOCK 256
#define SWEEP_GRID (WARPS_TOTAL / (SWEEP_BLOCK / 32))  // 320

// fused-2 iteration kernel config (R7 geometry: one plane per warp)
#define IT2_BLOCK 128
#define IT2_GRID (WARPS_TOTAL / (IT2_BLOCK / 32))      // 640

// Static scratch (no allocations allowed in kernel_launch)
__device__ float g_p[NIMG * HWSZ];     // sigmoid(output), kept for final reduction
__device__ float g_imgA[TOTALSZ];      // ping
__device__ float g_imgB[TOTALSZ];      // pong
__device__ float g_skel[TOTALSZ];      // skeleton accumulators (both streams)
__device__ double g_sums[NIMG][7];     // per-sample reduction accumulators

// ---------------------------------------------------------------------------
// float4 helpers
// ---------------------------------------------------------------------------
__device__ __forceinline__ float4 f44(float v) { return make_float4(v, v, v, v); }
__device__ __forceinline__ float4 min4(float4 a, float4 b) {
    return make_float4(fminf(a.x, b.x), fminf(a.y, b.y), fminf(a.z, b.z), fminf(a.w, b.w));
}
__device__ __forceinline__ float4 max4(float4 a, float4 b) {
    return make_float4(fmaxf(a.x, b.x), fmaxf(a.y, b.y), fmaxf(a.z, b.z), fmaxf(a.w, b.w));
}
__device__ __forceinline__ float4 vmin3(float4 a, float4 b, float4 c) { return min4(min4(a, b), c); }
__device__ __forceinline__ float4 vmax3(float4 a, float4 b, float4 c) { return max4(max4(a, b), c); }
__device__ __forceinline__ float4 hmin3(float4 v, int lane) {
    float L = __shfl_up_sync(0xffffffffu, v.w, 1);
    float R = __shfl_down_sync(0xffffffffu, v.x, 1);
    if (lane == 0)  L = INFINITY;
    if (lane == 31) R = INFINITY;
    float m01 = fminf(v.x, v.y), m23 = fminf(v.z, v.w);
    return make_float4(fminf(L, m01), fminf(m01, v.z), fminf(v.y, m23), fminf(m23, R));
}
__device__ __forceinline__ float4 hmax3(float4 v, int lane) {
    float L = __shfl_up_sync(0xffffffffu, v.w, 1);
    float R = __shfl_down_sync(0xffffffffu, v.x, 1);
    if (lane == 0)  L = -INFINITY;
    if (lane == 31) R = -INFINITY;
    float m01 = fmaxf(v.x, v.y), m23 = fmaxf(v.z, v.w);
    return make_float4(fmaxf(L, m01), fmaxf(m01, v.z), fmaxf(v.y, m23), fmaxf(m23, R));
}
__device__ __forceinline__ float4 relu_sub(float4 a, float4 b) {
    return make_float4(fmaxf(0.0f, a.x - b.x), fmaxf(0.0f, a.y - b.y),
                       fmaxf(0.0f, a.z - b.z), fmaxf(0.0f, a.w - b.w));
}
__device__ __forceinline__ float4 maskneg(float4 v, bool ok) {
    return ok ? v : f44(-INFINITY);
}
__device__ __forceinline__ void skel_upd(float4& s, float4 d) {
    s.x += fmaxf(0.0f, fmaf(-s.x, d.x, d.x));
    s.y += fmaxf(0.0f, fmaf(-s.y, d.y, d.y));
    s.z += fmaxf(0.0f, fmaf(-s.z, d.z, d.z));
    s.w += fmaxf(0.0f, fmaf(-s.w, d.w, d.w));
}

// ---------------------------------------------------------------------------
// Init: p = sigmoid(output); imgA[stream0] = p, imgA[stream1] = target
// ---------------------------------------------------------------------------
__global__ void k_init(const float4* __restrict__ out, const float4* __restrict__ tgt) {
    int i = blockIdx.x * blockDim.x + threadIdx.x;
    int stride = gridDim.x * blockDim.x;
    float4* gp = (float4*)g_p;
    float4* ga = (float4*)g_imgA;
    float4* gb = (float4*)(g_imgA + NIMG * HWSZ);
    const int n4 = NIMG * HWSZ / 4;
    for (; i < n4; i += stride) {
        float4 o = out[i];
        float4 v;
        v.x = 1.0f / (1.0f + expf(-o.x));
        v.y = 1.0f / (1.0f + expf(-o.y));
        v.z = 1.0f / (1.0f + expf(-o.z));
        v.w = 1.0f / (1.0f + expf(-o.w));
        gp[i] = v;
        ga[i] = v;
        gb[i] = tgt[i];
    }
}

// ---------------------------------------------------------------------------
// Warp-sweep open-init:  skel = relu(img - dilate(erode(img)))
// ---------------------------------------------------------------------------
__global__ void __launch_bounds__(SWEEP_BLOCK, 3) k_open_init() {
    const int lane = threadIdx.x & 31;
    const int gw = (blockIdx.x * SWEEP_BLOCK + threadIdx.x) >> 5;
    const int strip = gw % STRIPS;
    const int t = gw / STRIPS;
    const int chunk = t & (CHUNKS - 1);
    const int z = t >> 5;

    const float* __restrict__ src = g_imgA + z * HWSZ;
    float* __restrict__ skel = g_skel + z * HWSZ;

    const int c0 = strip * 120 - 4 + 4 * lane;
    const bool colok = (c0 >= 0) && (c0 < WW);
    const bool stok = (lane >= 1) && (lane <= 30) && (c0 < WW);
    const int r0 = chunk * CHUNK_ROWS;
    const int ylim = r0 + 2;

    int y = r0 - 2;
    const float* srcp = src + y * WW + c0;
    float* const skb = skel + c0;

    float4 ia = f44(INFINITY), ib = f44(INFINITY), ic;
    float4 ha = f44(-INFINITY), hb = f44(-INFINITY), hc;

#define OPEN_STEP(IA, IB, IC, HA, HB, HC)                                      \
    {                                                                          \
        bool ldok = colok && ((unsigned)y < (unsigned)HH);                     \
        IC = ldok ? *(const float4*)srcp : f44(INFINITY);                      \
        float4 e1_ = min4(vmin3(IA, IB, IC), hmin3(IB, lane));                 \
        if (!colok || (unsigned)(y - 1) >= (unsigned)HH) e1_ = f44(-INFINITY); \
        HC = hmax3(e1_, lane);                                                 \
        if (y >= ylim) {                                                       \
            float4 d_ = vmax3(HA, HB, HC);                                     \
            if (stok) {                                                        \
                float4 o_ = relu_sub(IA, d_);                                  \
                *(float4*)(skb + (y - 2) * WW) = o_;                           \
            }                                                                  \
        }                                                                      \
        ++y;                                                                   \
        srcp += WW;                                                            \
    }

#pragma unroll 1
    for (int k = 0; k < 6; ++k) {
        OPEN_STEP(ia, ib, ic, ha, hb, hc);
        OPEN_STEP(ib, ic, ia, hb, hc, ha);
        OPEN_STEP(ic, ia, ib, hc, ha, hb);
    }
    OPEN_STEP(ia, ib, ic, ha, hb, hc);
    OPEN_STEP(ib, ic, ia, hb, hc, ha);
#undef OPEN_STEP
}

// ---------------------------------------------------------------------------
// Fused TWO skeleton iterations, fully unrolled 24-step sweep.
// Step S (y = r0 + S - 4):
//   I[S%3]  = img row y (prefetched)
//   E[S%3]  = E1[y-1] = erode(I)
//   F[S%3]  = E2[y-2] = erode(E1)    (iter2's new img)
//   H[S%3]  = hmax(mask(E2[y-2]))
//   B[S%3]  = hmax(mask(E3[y-3]))    where E3 = erode(E2)
//   S>=7 : D1 = vmax(H) -> delta1[y-3] (saved in dprev), prefetch skel row
//   S>=8 : D2 = vmax(B) -> delta2[y-4]; skel row y-4 updated w/ both deltas;
//          img row y-4 = E2[y-4] written.
// Guards are compile-time in S => pipeline-fill dead compute is DCE'd.
// IN=true (interior warps): all bounds masks removed at compile time.
// ---------------------------------------------------------------------------
template<bool IN>
__device__ __forceinline__ void it2_body(
    const float* __restrict__ src, float* __restrict__ dst,
    float* __restrict__ skel, int lane, int c0, int r0)
{
    const bool colok = IN || ((c0 >= 0) && (c0 < WW));
    const bool stok = (lane >= 1) && (lane <= 30) && (IN || (c0 < WW));

    const float* srcp = src + (r0 - 4) * WW + c0;
    float* const skb = skel + c0;
    float* const dsb = dst + c0;

    float4 pf;
    {
        bool ldok = colok && (IN || (unsigned)(r0 - 4) < (unsigned)HH);
        pf = ldok ? *(const float4*)srcp : f44(INFINITY);
        srcp += WW;
    }

    float4 I[3], E[3], F[3], H[3], B[3];
#pragma unroll
    for (int i = 0; i < 3; ++i) {
        I[i] = f44(INFINITY); E[i] = f44(INFINITY); F[i] = f44(INFINITY);
        H[i] = f44(-INFINITY); B[i] = f44(-INFINITY);
    }
    float4 dprev = f44(0.0f), spf = f44(0.0f);

#define STEP(S)                                                                \
    {                                                                          \
        const int y = r0 + (S) - 4;                                            \
        float4 icur = pf;                                                      \
        {                                                                      \
            bool ldok = colok && (IN || (unsigned)(y + 1) < (unsigned)HH);     \
            pf = ldok ? *(const float4*)srcp : f44(INFINITY);                  \
            srcp += WW;                                                        \
        }                                                                      \
        I[(S) % 3] = icur;                                                     \
        E[(S) % 3] = min4(vmin3(I[0], I[1], I[2]),                             \
                          hmin3(I[((S) + 2) % 3], lane));                      \
        F[(S) % 3] = min4(vmin3(E[0], E[1], E[2]),                             \
                          hmin3(E[((S) + 2) % 3], lane));                      \
        {                                                                      \
            bool okH = IN || (colok && (unsigned)(y - 2) < (unsigned)HH);      \
            H[(S) % 3] = hmax3(maskneg(F[(S) % 3], okH), lane);                \
        }                                                                      \
        {                                                                      \
            float4 e3_ = min4(vmin3(F[0], F[1], F[2]),                         \
                              hmin3(F[((S) + 2) % 3], lane));                  \
            bool okB = IN || (colok && (unsigned)(y - 3) < (unsigned)HH);      \
            B[(S) % 3] = hmax3(maskneg(e3_, okB), lane);                       \
        }                                                                      \
        if ((S) >= 8) {                                                        \
            float4 D2 = vmax3(B[0], B[1], B[2]);                               \
            if (stok) {                                                        \
                float4 d2 = relu_sub(F[((S) + 1) % 3], D2);  /* E2[y-4] */     \
                float4 s = spf;                                                \
                skel_upd(s, dprev);                                            \
                skel_upd(s, d2);                                               \
                *(float4*)(skb + (y - 4) * WW) = s;                            \
                *(float4*)(dsb + (y - 4) * WW) = F[((S) + 1) % 3];             \
            }                                                                  \
        }                                                                      \
        if ((S) >= 7 && (S) < 23) {                                            \
            float4 D1 = vmax3(H[0], H[1], H[2]);                               \
            dprev = relu_sub(E[((S) + 1) % 3], D1);          /* E1[y-3] */     \
            if (stok) spf = *(const float4*)(skb + (y - 3) * WW);              \
        }                                                                      \
    }

    STEP(0)  STEP(1)  STEP(2)  STEP(3)  STEP(4)  STEP(5)
    STEP(6)  STEP(7)  STEP(8)  STEP(9)  STEP(10) STEP(11)
    STEP(12) STEP(13) STEP(14) STEP(15) STEP(16) STEP(17)
    STEP(18) STEP(19) STEP(20) STEP(21) STEP(22) STEP(23)
#undef STEP
}

__global__ void __launch_bounds__(IT2_BLOCK, 4) k_iter2(int flip) {
    const int lane = threadIdx.x & 31;
    const int gw = (blockIdx.x * IT2_BLOCK + threadIdx.x) >> 5;
    const int strip = gw % STRIPS;
    const int t = gw / STRIPS;
    const int chunk = t & (CHUNKS - 1);
    const int z = t >> 5;

    const float* __restrict__ src = (flip ? g_imgB : g_imgA) + z * HWSZ;
    float* __restrict__ dst = (flip ? g_imgA : g_imgB) + z * HWSZ;
    float* __restrict__ skel = g_skel + z * HWSZ;

    const int c0 = strip * 120 - 4 + 4 * lane;
    const int r0 = chunk * CHUNK_ROWS;

    // interior: every touched row/col strictly in range for ALL lanes
    const bool interior = (chunk >= 1) && (chunk <= 30) &&
                          (strip >= 1) && (strip <= 3);
    if (interior)
        it2_body<true>(src, dst, skel, lane, c0, r0);
    else
        it2_body<false>(src, dst, skel, lane, c0, r0);
}

// ---------------------------------------------------------------------------
// Reductions
// ---------------------------------------------------------------------------
__global__ void k_zero() {
    int t = threadIdx.x;
    if (t < NIMG * 7) ((double*)g_sums)[t] = 0.0;
}

__global__ void k_reduce(const float* __restrict__ tgt) {
    const int n = blockIdx.y;
    const float4* __restrict__ sp = (const float4*)(g_skel + n * HWSZ);
    const float4* __restrict__ sl = (const float4*)(g_skel + (NIMG + n) * HWSZ);
    const float4* __restrict__ pp = (const float4*)(g_p + n * HWSZ);
    const float4* __restrict__ tt = (const float4*)(tgt + n * HWSZ);
    const int n4 = HWSZ / 4;

    double a0 = 0, a1 = 0, a2 = 0, a3 = 0, a4 = 0, a5 = 0, a6 = 0;
    for (int i = blockIdx.x * blockDim.x + threadIdx.x; i < n4;
         i += gridDim.x * blockDim.x) {
        float4 s1 = sp[i], s2 = sl[i], pv = pp[i], tv = tt[i];
        a0 += (double)(s1.x * tv.x + s1.y * tv.y + s1.z * tv.z + s1.w * tv.w);
        a1 += (double)(s1.x + s1.y + s1.z + s1.w);
        a2 += (double)(s2.x * pv.x + s2.y * pv.y + s2.z * pv.z + s2.w * pv.w);
        a3 += (double)(s2.x + s2.y + s2.z + s2.w);
        a4 += (double)(pv.x * tv.x + pv.y * tv.y + pv.z * tv.z + pv.w * tv.w);
        a5 += (double)(pv.x + pv.y + pv.z + pv.w);
        a6 += (double)(tv.x + tv.y + tv.z + tv.w);
    }
#pragma unroll
    for (int o = 16; o > 0; o >>= 1) {
        a0 += __shfl_down_sync(0xffffffffu, a0, o);
        a1 += __shfl_down_sync(0xffffffffu, a1, o);
        a2 += __shfl_down_sync(0xffffffffu, a2, o);
        a3 += __shfl_down_sync(0xffffffffu, a3, o);
        a4 += __shfl_down_sync(0xffffffffu, a4, o);
        a5 += __shfl_down_sync(0xffffffffu, a5, o);
        a6 += __shfl_down_sync(0xffffffffu, a6, o);
    }
    if ((threadIdx.x & 31) == 0) {
        atomicAdd(&g_sums[n][0], a0);
        atomicAdd(&g_sums[n][1], a1);
        atomicAdd(&g_sums[n][2], a2);
        atomicAdd(&g_sums[n][3], a3);
        atomicAdd(&g_sums[n][4], a4);
        atomicAdd(&g_sums[n][5], a5);
        atomicAdd(&g_sums[n][6], a6);
    }
}

__global__ void k_final(float* __restrict__ out, int out_size) {
    if (threadIdx.x == 0 && blockIdx.x == 0) {
        const double smooth = 1.0;
        double cl = 0.0, dice = 0.0;
        for (int n = 0; n < NIMG; n++) {
            double A = g_sums[n][0], B = g_sums[n][1], C = g_sums[n][2],
                   D = g_sums[n][3], E = g_sums[n][4], F = g_sums[n][5],
                   G = g_sums[n][6];
            double tprec = (A + smooth) / (B + smooth);
            double tsens = (C + smooth) / (D + smooth);
            cl += 1.0 - 2.0 * tprec * tsens / (tprec + tsens);
            dice += 1.0 - 2.0 * (E + smooth) / (F + G + smooth);
        }
        cl /= NIMG;
        dice /= NIMG;
        float loss = (float)(0.7 * dice + 0.3 * cl);
        for (int i = 0; i < out_size; i++) out[i] = loss;
    }
}

// ---------------------------------------------------------------------------
extern "C" void kernel_launch(void* const* d_in, const int* in_sizes, int n_in,
                              void* d_out, int out_size) {
    const float* output = (const float*)d_in[0];
    const float* target = (const float*)d_in[1];
    float* out = (float*)d_out;

    k_init<<<1024, 256>>>((const float4*)output, (const float4*)target);

    k_open_init<<<SWEEP_GRID, SWEEP_BLOCK>>>();

    // 50 iterations = 25 fused-2 launches
    for (int j = 0; j < NITER / 2; ++j) {
        k_iter2<<<IT2_GRID, IT2_BLOCK>>>(j & 1);
    }

    k_zero<<<1, 64>>>();
    k_reduce<<<dim3(32, NIMG), 256>>>(target);
    k_final<<<1, 32>>>(out, out_size);
}